// round 1
// baseline (speedup 1.0000x reference)
#include <cuda_runtime.h>
#include <cstdint>

// Problem shape (fixed by setup_inputs)
#define BATCH 4
#define TLEN  4096
#define HDIM  1024
#define MROWS (BATCH * TLEN)   // 16384
#define WIN   8
#define WSZ   9                // window + 1 taps

// Scratch for q, k, v (device globals: allocation rules forbid cudaMalloc)
__device__ float g_q[MROWS * HDIM];
__device__ float g_k[MROWS * HDIM];
__device__ float g_v[MROWS * HDIM];

// ---------------- GEMM config ----------------
#define BM 128
#define BN 128
#define BK 16
#define SSTRIDE (BK + 4)       // 20 floats: (20*g + tg) % 32 covers all banks
#define GEMM_THREADS 256

__device__ __forceinline__ uint32_t f2tf32(float x) {
    uint32_t r;
    asm("cvt.rna.tf32.f32 %0, %1;" : "=r"(r) : "f"(x));
    return r;
}

__device__ __forceinline__ void cp_async16(void* sptr, const void* gptr) {
    uint32_t s = (uint32_t)__cvta_generic_to_shared(sptr);
    asm volatile("cp.async.cg.shared.global [%0], [%1], 16;\n" :: "r"(s), "l"(gptr));
}
__device__ __forceinline__ void cp_commit() {
    asm volatile("cp.async.commit_group;\n" ::: "memory");
}
template<int N>
__device__ __forceinline__ void cp_wait() {
    asm volatile("cp.async.wait_group %0;\n" :: "n"(N) : "memory");
}

__device__ __forceinline__ void mma_tf32(float c[4], const uint32_t a[4], const uint32_t b[2]) {
    asm volatile(
        "mma.sync.aligned.m16n8k8.row.col.f32.tf32.tf32.f32 "
        "{%0,%1,%2,%3}, {%4,%5,%6,%7}, {%8,%9}, {%0,%1,%2,%3};\n"
        : "+f"(c[0]), "+f"(c[1]), "+f"(c[2]), "+f"(c[3])
        : "r"(a[0]), "r"(a[1]), "r"(a[2]), "r"(a[3]), "r"(b[0]), "r"(b[1]));
}

// D[m,n] = sum_k X[m,k] * W[n,k] + bias[n]    (i.e. X @ W^T + b)
__global__ __launch_bounds__(GEMM_THREADS)
void qkv_gemm_kernel(const float* __restrict__ X,
                     const float* __restrict__ Wq, const float* __restrict__ bq,
                     const float* __restrict__ Wk, const float* __restrict__ bk,
                     const float* __restrict__ Wv, const float* __restrict__ bv)
{
    const float* W; const float* bias; float* out;
    int z = blockIdx.z;
    if (z == 0)      { W = Wq; bias = bq; out = g_q; }
    else if (z == 1) { W = Wk; bias = bk; out = g_k; }
    else             { W = Wv; bias = bv; out = g_v; }

    __shared__ __align__(16) float As[2][BM * SSTRIDE];
    __shared__ __align__(16) float Bs[2][BN * SSTRIDE];

    const int tid  = threadIdx.x;
    const int m0   = blockIdx.x * BM;
    const int n0   = blockIdx.y * BN;

    // Global->smem load mapping: 128x16 tile = 512 float4; 2 per thread per matrix.
    const int rv = tid >> 2;       // 0..63
    const int cv = tid & 3;        // 0..3 (float4 column)

    const int warp = tid >> 5;
    const int lane = tid & 31;
    const int wm = (warp & 3) * 32;    // warp row offset in block tile
    const int wn = (warp >> 2) * 64;   // warp col offset
    const int g  = lane >> 2;          // 0..7
    const int tg = lane & 3;           // 0..3

    float c[2][8][4];
    #pragma unroll
    for (int mt = 0; mt < 2; ++mt)
        #pragma unroll
        for (int nt = 0; nt < 8; ++nt)
            #pragma unroll
            for (int i = 0; i < 4; ++i) c[mt][nt][i] = 0.f;

    const int NK = HDIM / BK;   // 64

    auto load_tile = [&](int kt, int buf) {
        const int k0 = kt * BK;
        #pragma unroll
        for (int i = 0; i < 2; ++i) {
            int r = rv + i * 64;
            cp_async16(&As[buf][r * SSTRIDE + cv * 4], X + (size_t)(m0 + r) * HDIM + k0 + cv * 4);
            cp_async16(&Bs[buf][r * SSTRIDE + cv * 4], W + (size_t)(n0 + r) * HDIM + k0 + cv * 4);
        }
    };

    load_tile(0, 0);
    cp_commit();

    for (int kt = 0; kt < NK; ++kt) {
        const int buf = kt & 1;
        if (kt + 1 < NK) {
            load_tile(kt + 1, buf ^ 1);
            cp_commit();
            cp_wait<1>();
        } else {
            cp_wait<0>();
        }
        __syncthreads();

        const float* Ab = As[buf];
        const float* Bb = Bs[buf];

        #pragma unroll
        for (int kk = 0; kk < BK; kk += 8) {
            uint32_t a[2][4], bf[8][2];
            #pragma unroll
            for (int mt = 0; mt < 2; ++mt) {
                int mrow = wm + mt * 16 + g;
                a[mt][0] = f2tf32(Ab[(mrow)     * SSTRIDE + kk + tg]);
                a[mt][1] = f2tf32(Ab[(mrow + 8) * SSTRIDE + kk + tg]);
                a[mt][2] = f2tf32(Ab[(mrow)     * SSTRIDE + kk + tg + 4]);
                a[mt][3] = f2tf32(Ab[(mrow + 8) * SSTRIDE + kk + tg + 4]);
            }
            #pragma unroll
            for (int nt = 0; nt < 8; ++nt) {
                int ncol = wn + nt * 8 + g;
                bf[nt][0] = f2tf32(Bb[ncol * SSTRIDE + kk + tg]);
                bf[nt][1] = f2tf32(Bb[ncol * SSTRIDE + kk + tg + 4]);
            }
            #pragma unroll
            for (int mt = 0; mt < 2; ++mt)
                #pragma unroll
                for (int nt = 0; nt < 8; ++nt)
                    mma_tf32(c[mt][nt], a[mt], bf[nt]);
        }
        __syncthreads();
    }

    // Epilogue: add bias, write fp32
    #pragma unroll
    for (int mt = 0; mt < 2; ++mt) {
        #pragma unroll
        for (int nt = 0; nt < 8; ++nt) {
            int row = m0 + wm + mt * 16 + g;
            int col = n0 + wn + nt * 8 + 2 * tg;
            float b0 = bias[col], b1 = bias[col + 1];
            *(float2*)(out + (size_t)row * HDIM + col) =
                make_float2(c[mt][nt][0] + b0, c[mt][nt][1] + b1);
            *(float2*)(out + (size_t)(row + 8) * HDIM + col) =
                make_float2(c[mt][nt][2] + b0, c[mt][nt][3] + b1);
        }
    }
}

// ---------------- Sliding-window attention ----------------
// One block per (b, t) row. 256 threads; each thread covers 4 of the 1024 dims.
__global__ __launch_bounds__(256)
void attn_kernel(float* __restrict__ out)
{
    const int row = blockIdx.x;            // b*TLEN + t
    const int t   = row & (TLEN - 1);
    const int tid = threadIdx.x;

    __shared__ float red[8][WSZ];
    __shared__ float attn_s[WSZ];

    const float* __restrict__ qrow = g_q + (size_t)row * HDIM;
    const int wstart = (t < WIN) ? (WIN - t) : 0;

    float acc[WSZ];
    #pragma unroll
    for (int w = 0; w < WSZ; ++w) acc[w] = 0.f;

    #pragma unroll
    for (int i = 0; i < HDIM / 256; ++i) {
        const int h = tid + i * 256;
        const float qv = qrow[h];
        #pragma unroll
        for (int w = 0; w < WSZ; ++w) {
            if (w >= wstart)
                acc[w] += qv * g_k[(size_t)(row - WIN + w) * HDIM + h];
        }
    }

    // Warp reduce each tap, then stash per-warp partials
    #pragma unroll
    for (int w = 0; w < WSZ; ++w) {
        float v = acc[w];
        #pragma unroll
        for (int off = 16; off; off >>= 1)
            v += __shfl_down_sync(0xFFFFFFFFu, v, off);
        if ((tid & 31) == 0) red[tid >> 5][w] = v;
    }
    __syncthreads();

    if (tid == 0) {
        float s[WSZ];
        float mx = -1e30f;
        #pragma unroll
        for (int w = 0; w < WSZ; ++w) {
            if (w >= wstart) {
                float v = 0.f;
                #pragma unroll
                for (int j = 0; j < 8; ++j) v += red[j][w];
                s[w] = v * 0.03125f;   // 1/sqrt(1024)
                mx = fmaxf(mx, s[w]);
            }
        }
        float denom = 0.f;
        #pragma unroll
        for (int w = 0; w < WSZ; ++w) {
            float e = (w >= wstart) ? __expf(s[w] - mx) : 0.f;
            attn_s[w] = e;
            denom += e;
        }
        float inv = 1.f / denom;
        #pragma unroll
        for (int w = 0; w < WSZ; ++w) attn_s[w] *= inv;
    }
    __syncthreads();

    float aw[WSZ];
    #pragma unroll
    for (int w = 0; w < WSZ; ++w) aw[w] = attn_s[w];

    #pragma unroll
    for (int i = 0; i < HDIM / 256; ++i) {
        const int h = tid + i * 256;
        float o = 0.f;
        #pragma unroll
        for (int w = 0; w < WSZ; ++w) {
            if (w >= wstart)
                o += aw[w] * g_v[(size_t)(row - WIN + w) * HDIM + h];
        }
        out[(size_t)row * HDIM + h] = o;
    }
}

extern "C" void kernel_launch(void* const* d_in, const int* in_sizes, int n_in,
                              void* d_out, int out_size)
{
    const float* states = (const float*)d_in[0];
    const float* Wq = (const float*)d_in[1];
    const float* bq = (const float*)d_in[2];
    const float* Wk = (const float*)d_in[3];
    const float* bk = (const float*)d_in[4];
    const float* Wv = (const float*)d_in[5];
    const float* bv = (const float*)d_in[6];
    float* out = (float*)d_out;

    dim3 grid(MROWS / BM, HDIM / BN, 3);   // 128 x 8 x 3
    qkv_gemm_kernel<<<grid, GEMM_THREADS>>>(states, Wq, bq, Wk, bk, Wv, bv);
    attn_kernel<<<MROWS, 256>>>(out);
}

// round 3
// speedup vs baseline: 2.2311x; 2.2311x over previous
#include <cuda_runtime.h>
#include <cuda_fp16.h>
#include <cstdint>

#define BATCH 4
#define TLEN  4096
#define HDIM  1024
#define MROWS (BATCH * TLEN)   // 16384
#define WIN   8
#define WSZ   9

// Scratch (device globals; cudaMalloc forbidden)
__device__ float  g_q[MROWS * HDIM];
__device__ float  g_k[MROWS * HDIM];
__device__ float  g_v[MROWS * HDIM];
__device__ __half g_xh[MROWS * HDIM];        // fp16 states
__device__ __half g_wh[3 * HDIM * HDIM];     // fp16 Wq|Wk|Wv

// ---------------- PTX helpers ----------------
__device__ __forceinline__ uint32_t smem_u32(const void* p) {
    uint32_t a;
    asm("{ .reg .u64 t; cvta.to.shared.u64 t, %1; cvt.u32.u64 %0, t; }" : "=r"(a) : "l"(p));
    return a;
}
__device__ __forceinline__ void cp_async16(uint32_t sdst, const void* g) {
    asm volatile("cp.async.cg.shared.global [%0], [%1], 16;" :: "r"(sdst), "l"(g));
}
__device__ __forceinline__ void cp_commit() {
    asm volatile("cp.async.commit_group;" ::: "memory");
}
template<int N>
__device__ __forceinline__ void cp_wait() {
    asm volatile("cp.async.wait_group %0;" :: "n"(N) : "memory");
}
__device__ __forceinline__ void ldmatrix_x4(uint32_t r[4], uint32_t addr) {
    asm volatile("ldmatrix.sync.aligned.m8n8.x4.shared.b16 {%0,%1,%2,%3}, [%4];"
                 : "=r"(r[0]), "=r"(r[1]), "=r"(r[2]), "=r"(r[3]) : "r"(addr));
}
__device__ __forceinline__ void mma_f16(float c[4], const uint32_t a[4], const uint32_t b[2]) {
    asm volatile(
        "mma.sync.aligned.m16n8k16.row.col.f32.f16.f16.f32 "
        "{%0,%1,%2,%3}, {%4,%5,%6,%7}, {%8,%9}, {%0,%1,%2,%3};"
        : "+f"(c[0]), "+f"(c[1]), "+f"(c[2]), "+f"(c[3])
        : "r"(a[0]), "r"(a[1]), "r"(a[2]), "r"(a[3]), "r"(b[0]), "r"(b[1]));
}

// ---------------- prepass: fp32 -> fp16 ----------------
__global__ __launch_bounds__(256) void conv_states_kernel(const float* __restrict__ x) {
    int i = blockIdx.x * 256 + threadIdx.x;         // float4 index, 4,194,304 total
    float4 v = ((const float4*)x)[i];
    __half2 h0 = __floats2half2_rn(v.x, v.y);
    __half2 h1 = __floats2half2_rn(v.z, v.w);
    ((__half2*)g_xh)[2 * i]     = h0;
    ((__half2*)g_xh)[2 * i + 1] = h1;
}
__global__ __launch_bounds__(256) void conv_w_kernel(const float* __restrict__ Wq,
                                                     const float* __restrict__ Wk,
                                                     const float* __restrict__ Wv) {
    int i = blockIdx.x * 256 + threadIdx.x;         // float4 index, 786,432 total
    const float* s; __half* d; int j;
    if (i < 262144)      { s = Wq; d = g_wh;           j = i; }
    else if (i < 524288) { s = Wk; d = g_wh + 1048576; j = i - 262144; }
    else                 { s = Wv; d = g_wh + 2097152; j = i - 524288; }
    float4 v = ((const float4*)s)[j];
    ((__half2*)d)[2 * j]     = __floats2half2_rn(v.x, v.y);
    ((__half2*)d)[2 * j + 1] = __floats2half2_rn(v.z, v.w);
}

// ---------------- fp16 QKV GEMM ----------------
// BM=128, BN=128, BK=32 halfs (64B rows). 3-stage cp.async pipeline.
// Smem swizzle: 16B chunk c of row r stored at chunk (c ^ ((r>>1)&3)).
#define BK 32
#define ROW_BYTES 64                  // BK * 2
#define TILE_BYTES (128 * ROW_BYTES)  // 8 KB
#define STAGE_BYTES (2 * TILE_BYTES)  // A + B = 16 KB
#define NSTAGE 3
#define NK (HDIM / BK)                // 32

__device__ __forceinline__ uint32_t sw_off(int r, int c) {   // bytes within one tile
    return (uint32_t)(r * ROW_BYTES + ((c ^ ((r >> 1) & 3)) << 4));
}

__global__ __launch_bounds__(256, 2)
void qkv_gemm_kernel(const float* __restrict__ bq,
                     const float* __restrict__ bk,
                     const float* __restrict__ bv)
{
    __shared__ __align__(128) char smem[NSTAGE * STAGE_BYTES];   // 48 KB
    const uint32_t sb = smem_u32(smem);

    const int tid  = threadIdx.x;
    const int warp = tid >> 5;
    const int lane = tid & 31;
    const int m0 = blockIdx.x * 128;
    const int n0 = blockIdx.y * 128;
    const int z  = blockIdx.z;

    const __half* Xh = g_xh;
    const __half* Wh = g_wh + (size_t)z * HDIM * HDIM;
    const float* bias = (z == 0) ? bq : (z == 1) ? bk : bv;
    float*       outp = (z == 0) ? g_q : (z == 1) ? g_k : g_v;

    const int wm = (warp & 3) * 32;    // warp row in block tile
    const int wn = (warp >> 2) * 64;   // warp col

    float c[2][8][4];
    #pragma unroll
    for (int mt = 0; mt < 2; ++mt)
        #pragma unroll
        for (int nt = 0; nt < 8; ++nt)
            #pragma unroll
            for (int i = 0; i < 4; ++i) c[mt][nt][i] = 0.f;

    // global->smem: 512 granules per tile; thread t does granules t, t+256
    const int r0g = tid >> 2;          // row for granule pass 0 (0..63)
    const int cg  = tid & 3;           // 16B chunk

    auto load_tile = [&](int kt, int buf) {
        const uint32_t sa = sb + buf * STAGE_BYTES;
        const uint32_t sbm = sa + TILE_BYTES;
        const int k0 = kt * BK;
        #pragma unroll
        for (int i = 0; i < 2; ++i) {
            int r = r0g + i * 64;
            cp_async16(sa + sw_off(r, cg),
                       Xh + (size_t)(m0 + r) * HDIM + k0 + cg * 8);
            cp_async16(sbm + sw_off(r, cg),
                       Wh + (size_t)(n0 + r) * HDIM + k0 + cg * 8);
        }
        cp_commit();
    };

    load_tile(0, 0);
    load_tile(1, 1);
    load_tile(2, 2);

    for (int kt = 0; kt < NK; ++kt) {
        const int buf = kt % NSTAGE;
        cp_wait<2>();
        __syncthreads();

        const uint32_t sa  = sb + buf * STAGE_BYTES;
        const uint32_t sbm = sa + TILE_BYTES;

        #pragma unroll
        for (int kk = 0; kk < BK; kk += 16) {
            // A fragments: 2 x ldmatrix.x4 (m16 x k16)
            uint32_t a[2][4];
            #pragma unroll
            for (int mt = 0; mt < 2; ++mt) {
                int row = wm + mt * 16 + (lane & 15);
                int ch  = (kk >> 3) + (lane >> 4);
                ldmatrix_x4(a[mt], sa + sw_off(row, ch));
            }
            // B fragments: 4 x ldmatrix.x4, each covers two n8 tiles
            uint32_t b[4][4];
            #pragma unroll
            for (int np = 0; np < 4; ++np) {
                int row = wn + np * 16 + (lane & 7) + ((lane >> 4) << 3);
                int ch  = (kk >> 3) + ((lane >> 3) & 1);
                ldmatrix_x4(b[np], sbm + sw_off(row, ch));
            }
            #pragma unroll
            for (int mt = 0; mt < 2; ++mt)
                #pragma unroll
                for (int nt = 0; nt < 8; ++nt)
                    mma_f16(c[mt][nt], a[mt], &b[nt >> 1][(nt & 1) * 2]);
        }
        __syncthreads();
        if (kt + NSTAGE < NK) load_tile(kt + NSTAGE, buf);
    }

    // Epilogue: add bias, fp32 stores
    const int g  = lane >> 2;
    const int tg = lane & 3;
    #pragma unroll
    for (int mt = 0; mt < 2; ++mt) {
        #pragma unroll
        for (int nt = 0; nt < 8; ++nt) {
            int row = m0 + wm + mt * 16 + g;
            int col = n0 + wn + nt * 8 + 2 * tg;
            float b0 = bias[col], b1 = bias[col + 1];
            *(float2*)(outp + (size_t)row * HDIM + col) =
                make_float2(c[mt][nt][0] + b0, c[mt][nt][1] + b1);
            *(float2*)(outp + (size_t)(row + 8) * HDIM + col) =
                make_float2(c[mt][nt][2] + b0, c[mt][nt][3] + b1);
        }
    }
}

// ---------------- sliding-window attention: warp per row ----------------
__global__ __launch_bounds__(256) void attn_kernel(float* __restrict__ out)
{
    const int warp = threadIdx.x >> 5;
    const int lane = threadIdx.x & 31;
    const int row  = blockIdx.x * 8 + warp;
    const int t    = row & (TLEN - 1);
    const int wstart = (t < WIN) ? (WIN - t) : 0;

    const float4* q4 = (const float4*)(g_q + (size_t)row * HDIM);

    float acc[WSZ];
    #pragma unroll
    for (int w = 0; w < WSZ; ++w) acc[w] = 0.f;

    #pragma unroll
    for (int i = 0; i < 8; ++i) {
        const int idx = lane + i * 32;       // float4 index 0..255
        const float4 qv = q4[idx];
        #pragma unroll
        for (int w = 0; w < WSZ; ++w) {
            if (w >= wstart) {
                const float4 kv = ((const float4*)(g_k + (size_t)(row - WIN + w) * HDIM))[idx];
                acc[w] += qv.x * kv.x + qv.y * kv.y + qv.z * kv.z + qv.w * kv.w;
            }
        }
    }

    float wgt[WSZ];
    float mx = -1e30f;
    #pragma unroll
    for (int w = 0; w < WSZ; ++w) {
        float v = acc[w];
        #pragma unroll
        for (int off = 16; off; off >>= 1)
            v += __shfl_xor_sync(0xFFFFFFFFu, v, off);
        float s = (w >= wstart) ? v * 0.03125f : -1e30f;   // 1/sqrt(1024)
        wgt[w] = s;
        mx = fmaxf(mx, s);
    }
    float den = 0.f;
    #pragma unroll
    for (int w = 0; w < WSZ; ++w) {
        float e = (w >= wstart) ? __expf(wgt[w] - mx) : 0.f;
        wgt[w] = e;
        den += e;
    }
    const float inv = 1.f / den;
    #pragma unroll
    for (int w = 0; w < WSZ; ++w) wgt[w] *= inv;

    float4* o4 = (float4*)(out + (size_t)row * HDIM);
    #pragma unroll
    for (int i = 0; i < 8; ++i) {
        const int idx = lane + i * 32;
        float4 o = make_float4(0.f, 0.f, 0.f, 0.f);
        #pragma unroll
        for (int w = 0; w < WSZ; ++w) {
            if (w >= wstart) {
                const float4 vv = ((const float4*)(g_v + (size_t)(row - WIN + w) * HDIM))[idx];
                o.x += wgt[w] * vv.x; o.y += wgt[w] * vv.y;
                o.z += wgt[w] * vv.z; o.w += wgt[w] * vv.w;
            }
        }
        o4[idx] = o;
    }
}

// ---------------- launch ----------------
extern "C" void kernel_launch(void* const* d_in, const int* in_sizes, int n_in,
                              void* d_out, int out_size)
{
    const float* states = (const float*)d_in[0];
    const float* Wq = (const float*)d_in[1];
    const float* bq = (const float*)d_in[2];
    const float* Wk = (const float*)d_in[3];
    const float* bk = (const float*)d_in[4];
    const float* Wv = (const float*)d_in[5];
    const float* bv = (const float*)d_in[6];
    float* out = (float*)d_out;

    conv_states_kernel<<<16384, 256>>>(states);
    conv_w_kernel<<<3072, 256>>>(Wq, Wk, Wv);

    dim3 grid(MROWS / 128, HDIM / 128, 3);   // 128 x 8 x 3
    qkv_gemm_kernel<<<grid, 256>>>(bq, bk, bv);

    attn_kernel<<<MROWS / 8, 256>>>(out);
}